// round 8
// baseline (speedup 1.0000x reference)
#include <cuda_runtime.h>

// DCT_18769007084406 — float4 loads, 192-thread half-strip CTAs, per-channel
// vertical DCT, YCbCr mix in epilogue, butterfly DCT, closed-form affine.
// x[32,3,512,512] fp32 -> out[32,192,64,64] fp32

#define NT 192
#define PITCH 36                      // conflict-free both stages (see analysis)
#define GF (24 * 8 * PITCH)           // 6912 floats = 27648 B

static __device__ constexpr float B4[8][4] = {
  { 0.35355339059327373f,  0.35355339059327373f,  0.35355339059327373f,  0.35355339059327373f },
  { 0.49039264020161522f,  0.41573480615127262f,  0.27778511650980114f,  0.09754516100806417f },
  { 0.46193976625564337f,  0.19134171618254492f, -0.19134171618254492f, -0.46193976625564337f },
  { 0.41573480615127262f, -0.09754516100806417f, -0.49039264020161522f, -0.27778511650980114f },
  { 0.35355339059327373f, -0.35355339059327373f, -0.35355339059327373f,  0.35355339059327373f },
  { 0.27778511650980114f, -0.49039264020161522f,  0.09754516100806417f,  0.41573480615127262f },
  { 0.19134171618254492f, -0.46193976625564337f,  0.46193976625564337f, -0.19134171618254492f },
  { 0.09754516100806417f, -0.27778511650980114f,  0.41573480615127262f, -0.49039264020161522f }
};

__global__ void __launch_bounds__(NT, 7)
dct_fused_kernel(const float* __restrict__ x,
                 const float* __restrict__ max_,
                 const float* __restrict__ min_,
                 const float* __restrict__ ycw,
                 float* __restrict__ out)
{
    __shared__ float  G[GF];          // [(c*64 + u*8 + j)*PITCH + bw]
    __shared__ float2 aff[192];

    const int t    = threadIdx.x;
    const int bx   = blockIdx.x;
    const int r    = bx >> 1;         // block-row 0..63
    const int half = bx & 1;          // 256-col half
    const int b    = blockIdx.y;

    {   // all 192 threads: one aff entry each
        const float mx = max_[b * 192 + t];
        const float mn = min_[b * 192 + t];
        const float d  = mx - mn + 1e-6f;
        const float rr = 1.0f / d;
        float r2 = rr * rr, r4 = r2 * r2, r8 = r4 * r4, r16 = r8 * r8;
        const float r32 = r16 * r16;
        aff[t] = make_float2(r32, -mn * (rr * (1.0f - r32) / (1.0f - rr)));
    }

    // ---- Stage A: one (channel, 4-col group) per thread, 8x LDG.128 -------
    const int c  = t >> 6;            // 0..2
    const int cg = t & 63;            // 4-col group within half; cols cg*4..+3
    const int j0 = (cg & 1) * 4;      // col%8 base: 0 or 4
    const int bw = cg >> 1;           // block-col within half: 0..31

    const float4* xr = (const float4*)(x + ((size_t)b * 3 + c) * 262144
                                         + (size_t)r * 8 * 512 + half * 256) + cg;

    float4 v[8];
    #pragma unroll
    for (int i = 0; i < 8; ++i)
        v[i] = __ldg(xr + i * 128);   // 512 floats = 128 float4 per image row

    const float4 s0 = make_float4(v[0].x + v[7].x, v[0].y + v[7].y, v[0].z + v[7].z, v[0].w + v[7].w);
    const float4 d0 = make_float4(v[0].x - v[7].x, v[0].y - v[7].y, v[0].z - v[7].z, v[0].w - v[7].w);
    const float4 s1 = make_float4(v[1].x + v[6].x, v[1].y + v[6].y, v[1].z + v[6].z, v[1].w + v[6].w);
    const float4 d1 = make_float4(v[1].x - v[6].x, v[1].y - v[6].y, v[1].z - v[6].z, v[1].w - v[6].w);
    const float4 s2 = make_float4(v[2].x + v[5].x, v[2].y + v[5].y, v[2].z + v[5].z, v[2].w + v[5].w);
    const float4 d2 = make_float4(v[2].x - v[5].x, v[2].y - v[5].y, v[2].z - v[5].z, v[2].w - v[5].w);
    const float4 s3 = make_float4(v[3].x + v[4].x, v[3].y + v[4].y, v[3].z + v[4].z, v[3].w + v[4].w);
    const float4 d3 = make_float4(v[3].x - v[4].x, v[3].y - v[4].y, v[3].z - v[4].z, v[3].w - v[4].w);

    float* Gc = G + (c * 64 + j0) * PITCH + bw;   // + u*8*PITCH + l*PITCH
    #pragma unroll
    for (int u = 0; u < 8; u += 2) {
        float4 e;
        e.x = fmaf(B4[u][0], s0.x, fmaf(B4[u][1], s1.x, fmaf(B4[u][2], s2.x, B4[u][3] * s3.x)));
        e.y = fmaf(B4[u][0], s0.y, fmaf(B4[u][1], s1.y, fmaf(B4[u][2], s2.y, B4[u][3] * s3.y)));
        e.z = fmaf(B4[u][0], s0.z, fmaf(B4[u][1], s1.z, fmaf(B4[u][2], s2.z, B4[u][3] * s3.z)));
        e.w = fmaf(B4[u][0], s0.w, fmaf(B4[u][1], s1.w, fmaf(B4[u][2], s2.w, B4[u][3] * s3.w)));
        float* Gu = Gc + u * 8 * PITCH;
        Gu[0 * PITCH] = e.x;  Gu[1 * PITCH] = e.y;
        Gu[2 * PITCH] = e.z;  Gu[3 * PITCH] = e.w;

        float4 o;
        o.x = fmaf(B4[u+1][0], d0.x, fmaf(B4[u+1][1], d1.x, fmaf(B4[u+1][2], d2.x, B4[u+1][3] * d3.x)));
        o.y = fmaf(B4[u+1][0], d0.y, fmaf(B4[u+1][1], d1.y, fmaf(B4[u+1][2], d2.y, B4[u+1][3] * d3.y)));
        o.z = fmaf(B4[u+1][0], d0.z, fmaf(B4[u+1][1], d1.z, fmaf(B4[u+1][2], d2.z, B4[u+1][3] * d3.z)));
        o.w = fmaf(B4[u+1][0], d0.w, fmaf(B4[u+1][1], d1.w, fmaf(B4[u+1][2], d2.w, B4[u+1][3] * d3.w)));
        float* Go = Gc + (u + 1) * 8 * PITCH;
        Go[0 * PITCH] = o.x;  Go[1 * PITCH] = o.y;
        Go[2 * PITCH] = o.z;  Go[3 * PITCH] = o.w;
    }

    __syncthreads();

    // ------- Stage B: channel mix (j-domain) + horizontal DCT + affine -----
    const int bwB = t & 31;           // 0..31
    const int cu0 = t >> 5;           // 0..5
    const size_t outb = (size_t)b * 192 * 4096 + (size_t)r * 64 + half * 32 + bwB;

    #pragma unroll
    for (int q = 0; q < 4; ++q) {
        const int cu = cu0 + q * 6;   // 0..23 == c*8 + u
        const int uu = cu & 7, cc = cu >> 3;

        float m[8];
        #pragma unroll
        for (int ci = 0; ci < 3; ++ci) {
            const float w = ycw[cc * 3 + ci];
            #pragma unroll
            for (int jj = 0; jj < 8; ++jj) {
                const float g = G[((ci * 8 + uu) * 8 + jj) * PITCH + bwB];
                m[jj] = (ci == 0) ? w * g : fmaf(w, g, m[jj]);
            }
        }

        const float s0b = m[0] + m[7], s1b = m[1] + m[6], s2b = m[2] + m[5], s3b = m[3] + m[4];
        const float d0b = m[0] - m[7], d1b = m[1] - m[6], d2b = m[2] - m[5], d3b = m[3] - m[4];

        const int kbase = cu * 8;     // k = c*64 + u*8 + v
        #pragma unroll
        for (int vv = 0; vv < 8; vv += 2) {
            float e = B4[vv][0] * s0b;
            e = fmaf(B4[vv][1], s1b, e);
            e = fmaf(B4[vv][2], s2b, e);
            e = fmaf(B4[vv][3], s3b, e);
            float2 sb = aff[kbase + vv];
            out[outb + (size_t)(kbase + vv) * 4096] = fmaf(e, sb.x, sb.y);

            float o = B4[vv + 1][0] * d0b;
            o = fmaf(B4[vv + 1][1], d1b, o);
            o = fmaf(B4[vv + 1][2], d2b, o);
            o = fmaf(B4[vv + 1][3], d3b, o);
            sb = aff[kbase + vv + 1];
            out[outb + (size_t)(kbase + vv + 1) * 4096] = fmaf(o, sb.x, sb.y);
        }
    }
}

extern "C" void kernel_launch(void* const* d_in, const int* in_sizes, int n_in,
                              void* d_out, int out_size)
{
    const float* x    = (const float*)d_in[0];
    const float* max_ = (const float*)d_in[1];
    const float* min_ = (const float*)d_in[2];
    const float* ycw  = (const float*)d_in[3];
    float* out = (float*)d_out;

    dim3 grid(128, 32);               // (block-row halves, batch)
    dct_fused_kernel<<<grid, NT>>>(x, max_, min_, ycw, out);
}

// round 9
// speedup vs baseline: 1.1125x; 1.1125x over previous
#include <cuda_runtime.h>

// DCT_18769007084406 — cp.async input staging (zero register pressure),
// smem-resident vertical DCT, YCbCr mix in epilogue, butterfly, closed-form affine.
// x[32,3,512,512] fp32 -> out[32,192,64,64] fp32

#define NT 256
#define PITCH 36                      // 4j+bw conflict-free (proven R3)
#define GF (24 * 8 * PITCH)           // 6912 floats
#define INF 6144                      // input strip: 3ch * 8rows * 256cols
#define SMEM_FLOATS (INF + GF + 2 * 192)
#define SMEM_BYTES (SMEM_FLOATS * 4)  // 53760 B

static __device__ constexpr float B4[8][4] = {
  { 0.35355339059327373f,  0.35355339059327373f,  0.35355339059327373f,  0.35355339059327373f },
  { 0.49039264020161522f,  0.41573480615127262f,  0.27778511650980114f,  0.09754516100806417f },
  { 0.46193976625564337f,  0.19134171618254492f, -0.19134171618254492f, -0.46193976625564337f },
  { 0.41573480615127262f, -0.09754516100806417f, -0.49039264020161522f, -0.27778511650980114f },
  { 0.35355339059327373f, -0.35355339059327373f, -0.35355339059327373f,  0.35355339059327373f },
  { 0.27778511650980114f, -0.49039264020161522f,  0.09754516100806417f,  0.41573480615127262f },
  { 0.19134171618254492f, -0.46193976625564337f,  0.46193976625564337f, -0.19134171618254492f },
  { 0.09754516100806417f, -0.27778511650980114f,  0.41573480615127262f, -0.49039264020161522f }
};

__global__ void __launch_bounds__(NT, 4)
dct_fused_kernel(const float* __restrict__ x,
                 const float* __restrict__ max_,
                 const float* __restrict__ min_,
                 const float* __restrict__ ycw,
                 float* __restrict__ out)
{
    extern __shared__ float sm[];
    float*  IN  = sm;                 // [c][i][col] : (c*8+i)*256 + col
    float*  G   = sm + INF;           // [(c*64 + u*8 + j)*PITCH + bw]
    float2* aff = (float2*)(sm + INF + GF);

    const int t    = threadIdx.x;
    const int bx   = blockIdx.x;
    const int r    = bx >> 1;         // block-row 0..63
    const int half = bx & 1;          // 256-col half
    const int b    = blockIdx.y;

    // ---- Issue all input copies first: 1536 x 16B cp.async, 6 per thread --
    const float* xg = x + (size_t)b * 3 * 262144 + (size_t)r * 8 * 512 + half * 256;
    const unsigned in_s = (unsigned)__cvta_generic_to_shared(IN);

    #pragma unroll
    for (int k = 0; k < 6; ++k) {
        const int idx = t + k * 256;  // 0..1535
        const int c   = idx >> 9;
        const int rem = idx & 511;
        const int i   = rem >> 6;
        const int cg4 = rem & 63;     // float4 index within 256-col row
        const float* gp = xg + (size_t)c * 262144 + i * 512 + cg4 * 4;
        asm volatile("cp.async.cg.shared.global [%0], [%1], 16;"
                     :: "r"(in_s + idx * 16), "l"(gp));
    }
    asm volatile("cp.async.commit_group;");

    // ---- Overlap: closed-form affine of the 32x repeated (t - min)/d ------
    if (t < 192) {
        const float mx = max_[b * 192 + t];
        const float mn = min_[b * 192 + t];
        const float d  = mx - mn + 1e-6f;
        const float rr = 1.0f / d;
        float r2 = rr * rr, r4 = r2 * r2, r8 = r4 * r4, r16 = r8 * r8;
        const float r32 = r16 * r16;
        aff[t] = make_float2(r32, -mn * (rr * (1.0f - r32) / (1.0f - rr)));
    }

    asm volatile("cp.async.wait_group 0;");
    __syncthreads();

    // ---- Stage A: vertical DCT from smem (stride-1 LDS, conflict-free) ----
    const int j  = t & 7;
    const int bw = t >> 3;            // 0..31

    #pragma unroll
    for (int c = 0; c < 3; ++c) {
        float v[8];
        #pragma unroll
        for (int i = 0; i < 8; ++i)
            v[i] = IN[(c * 8 + i) * 256 + t];

        const float s0 = v[0] + v[7], s1 = v[1] + v[6], s2 = v[2] + v[5], s3 = v[3] + v[4];
        const float d0 = v[0] - v[7], d1 = v[1] - v[6], d2 = v[2] - v[5], d3 = v[3] - v[4];

        float* Gc = G + (c * 64 + j) * PITCH + bw;
        #pragma unroll
        for (int u = 0; u < 8; u += 2) {
            float e = B4[u][0] * s0;
            e = fmaf(B4[u][1], s1, e);
            e = fmaf(B4[u][2], s2, e);
            e = fmaf(B4[u][3], s3, e);
            Gc[u * 8 * PITCH] = e;
            float o = B4[u + 1][0] * d0;
            o = fmaf(B4[u + 1][1], d1, o);
            o = fmaf(B4[u + 1][2], d2, o);
            o = fmaf(B4[u + 1][3], d3, o);
            Gc[(u + 1) * 8 * PITCH] = o;
        }
    }

    __syncthreads();

    // ---- Stage B: channel mix (j-domain) + horizontal DCT + affine --------
    const int bwB = t & 31;
    const int u   = t >> 5;           // 0..7
    const size_t outb = (size_t)b * 192 * 4096 + (size_t)r * 64 + half * 32 + bwB;

    #pragma unroll
    for (int q = 0; q < 3; ++q) {     // output (YCbCr) channel
        float m[8];
        #pragma unroll
        for (int c = 0; c < 3; ++c) {
            const float w = ycw[q * 3 + c];
            #pragma unroll
            for (int jj = 0; jj < 8; ++jj) {
                const float g = G[((c * 8 + u) * 8 + jj) * PITCH + bwB];
                m[jj] = (c == 0) ? w * g : fmaf(w, g, m[jj]);
            }
        }

        const float s0 = m[0] + m[7], s1 = m[1] + m[6], s2 = m[2] + m[5], s3 = m[3] + m[4];
        const float d0 = m[0] - m[7], d1 = m[1] - m[6], d2 = m[2] - m[5], d3 = m[3] - m[4];

        const int kbase = q * 64 + u * 8;
        #pragma unroll
        for (int vv = 0; vv < 8; vv += 2) {
            float e = B4[vv][0] * s0;
            e = fmaf(B4[vv][1], s1, e);
            e = fmaf(B4[vv][2], s2, e);
            e = fmaf(B4[vv][3], s3, e);
            float2 sb = aff[kbase + vv];
            out[outb + (size_t)(kbase + vv) * 4096] = fmaf(e, sb.x, sb.y);

            float o = B4[vv + 1][0] * d0;
            o = fmaf(B4[vv + 1][1], d1, o);
            o = fmaf(B4[vv + 1][2], d2, o);
            o = fmaf(B4[vv + 1][3], d3, o);
            sb = aff[kbase + vv + 1];
            out[outb + (size_t)(kbase + vv + 1) * 4096] = fmaf(o, sb.x, sb.y);
        }
    }
}

extern "C" void kernel_launch(void* const* d_in, const int* in_sizes, int n_in,
                              void* d_out, int out_size)
{
    const float* x    = (const float*)d_in[0];
    const float* max_ = (const float*)d_in[1];
    const float* min_ = (const float*)d_in[2];
    const float* ycw  = (const float*)d_in[3];
    float* out = (float*)d_out;

    cudaFuncSetAttribute(dct_fused_kernel,
                         cudaFuncAttributeMaxDynamicSharedMemorySize, SMEM_BYTES);

    dim3 grid(128, 32);               // (block-row halves, batch)
    dct_fused_kernel<<<grid, NT, SMEM_BYTES>>>(x, max_, min_, ycw, out);
}

// round 10
// speedup vs baseline: 1.1621x; 1.0446x over previous
#include <cuda_runtime.h>
#include <cstdint>

// DCT_18769007084406 — persistent pipelined CTAs: cp.async.bulk chunk ring (+mbarrier)
// decouples HBM latency from warp count. YCbCr mix in epilogue, butterfly DCT,
// closed-form affine. x[32,3,512,512] fp32 -> out[32,192,64,64] fp32

#define NT 256
#define GRID 456                      // 3 CTAs/SM x 152 SMs
#define PITCH 36                      // conflict-free both stages (R3-proven)
#define GF (24 * 8 * PITCH)           // 6912 floats
#define NBUF 4
#define CH_FLOATS 2048                // chunk = 1 channel x 8 rows x 256 cols
#define CH_BYTES 8192
#define BUF_FLOATS (NBUF * CH_FLOATS) // 8192
#define MBAR_F (BUF_FLOATS + GF + 2 * 192)     // float idx of mbars (byte%8==0)
#define SMEM_BYTES ((MBAR_F + 16) * 4)         // ~62 KB

static __device__ constexpr float B4[8][4] = {
  { 0.35355339059327373f,  0.35355339059327373f,  0.35355339059327373f,  0.35355339059327373f },
  { 0.49039264020161522f,  0.41573480615127262f,  0.27778511650980114f,  0.09754516100806417f },
  { 0.46193976625564337f,  0.19134171618254492f, -0.19134171618254492f, -0.46193976625564337f },
  { 0.41573480615127262f, -0.09754516100806417f, -0.49039264020161522f, -0.27778511650980114f },
  { 0.35355339059327373f, -0.35355339059327373f, -0.35355339059327373f,  0.35355339059327373f },
  { 0.27778511650980114f, -0.49039264020161522f,  0.09754516100806417f,  0.41573480615127262f },
  { 0.19134171618254492f, -0.46193976625564337f,  0.46193976625564337f, -0.19134171618254492f },
  { 0.09754516100806417f, -0.27778511650980114f,  0.41573480615127262f, -0.49039264020161522f }
};

__device__ __forceinline__ void mbar_wait(uint32_t addr, uint32_t parity) {
    asm volatile(
        "{\n\t"
        ".reg .pred P;\n\t"
        "W_%=:\n\t"
        "mbarrier.try_wait.parity.acquire.cta.shared::cta.b64 P, [%0], %1, 0x989680;\n\t"
        "@P bra.uni D_%=;\n\t"
        "bra.uni W_%=;\n\t"
        "D_%=:\n\t"
        "}"
        :: "r"(addr), "r"(parity) : "memory");
}

// Issue one 8 KB chunk (strip s, channel c) as 8x1KB bulk copies into ring slot.
__device__ __forceinline__ void issue_chunk(const float* __restrict__ x,
                                            int cta, int n,
                                            uint32_t buf_s, uint32_t mbar_s)
{
    const int s = cta + (n / 3) * GRID;
    const int c = n % 3;
    const int b = s >> 7, rh = s & 127, r = rh >> 1, half = rh & 1;
    const float* src = x + (size_t)(b * 3 + c) * 262144 + r * 8 * 512 + half * 256;
    const uint32_t dst = buf_s + (uint32_t)(n & 3) * CH_BYTES;
    const uint32_t bar = mbar_s + (uint32_t)(n & 3) * 8;

    asm volatile("mbarrier.arrive.expect_tx.shared.b64 _, [%0], %1;"
                 :: "r"(bar), "r"((uint32_t)CH_BYTES) : "memory");
    #pragma unroll
    for (int i = 0; i < 8; ++i)
        asm volatile("cp.async.bulk.shared::cluster.global.mbarrier::complete_tx::bytes "
                     "[%0], [%1], %2, [%3];"
                     :: "r"(dst + i * 1024), "l"(src + i * 512),
                        "r"(1024), "r"(bar) : "memory");
}

__global__ void __launch_bounds__(NT)
dct_fused_kernel(const float* __restrict__ x,
                 const float* __restrict__ max_,
                 const float* __restrict__ min_,
                 const float* __restrict__ ycw,
                 float* __restrict__ out)
{
    extern __shared__ float sm[];
    float*  BUF = sm;                 // [4][2048]
    float*  G   = sm + BUF_FLOATS;    // [(c*64 + u*8 + j)*PITCH + bw]
    float2* aff = (float2*)(sm + BUF_FLOATS + GF);

    const uint32_t buf_s  = (uint32_t)__cvta_generic_to_shared(BUF);
    const uint32_t mbar_s = (uint32_t)__cvta_generic_to_shared(sm + MBAR_F);

    const int t   = threadIdx.x;
    const int cta = blockIdx.x;

    if (t == 0) {
        #pragma unroll
        for (int i = 0; i < NBUF; ++i)
            asm volatile("mbarrier.init.shared.b64 [%0], 1;"
                         :: "r"(mbar_s + i * 8) : "memory");
    }
    __syncthreads();

    const int nstrips = (4095 - cta) / GRID + 1;
    const int nchunks = 3 * nstrips;

    if (t == 0) {
        const int pro = nchunks < NBUF ? nchunks : NBUF;
        for (int n = 0; n < pro; ++n)
            issue_chunk(x, cta, n, buf_s, mbar_s);
    }

    const int j   = t & 7;
    const int bw  = t >> 3;           // 0..31
    const int bwB = t & 31;
    const int u   = t >> 5;           // 0..7

    int n = 0;
    for (int k = 0; k < nstrips; ++k) {
        const int s = cta + k * GRID;
        const int b = s >> 7, rh = s & 127, r = rh >> 1, half = rh & 1;

        // issue aff input loads early; latency hides under chunk waits
        float mx = 0.f, mn = 0.f;
        if (t < 192) { mx = max_[b * 192 + t]; mn = min_[b * 192 + t]; }

        // ---- Stage A: 3 chunks -> vertical DCT into G --------------------
        #pragma unroll
        for (int c = 0; c < 3; ++c, ++n) {
            mbar_wait(mbar_s + (n & 3) * 8, (n >> 2) & 1);

            const float* IN = BUF + (n & 3) * CH_FLOATS;
            float v[8];
            #pragma unroll
            for (int i = 0; i < 8; ++i)
                v[i] = IN[i * 256 + t];

            const float s0 = v[0] + v[7], s1 = v[1] + v[6], s2 = v[2] + v[5], s3 = v[3] + v[4];
            const float d0 = v[0] - v[7], d1 = v[1] - v[6], d2 = v[2] - v[5], d3 = v[3] - v[4];

            float* Gc = G + (c * 64 + j) * PITCH + bw;
            #pragma unroll
            for (int uu = 0; uu < 8; uu += 2) {
                float e = B4[uu][0] * s0;
                e = fmaf(B4[uu][1], s1, e);
                e = fmaf(B4[uu][2], s2, e);
                e = fmaf(B4[uu][3], s3, e);
                Gc[uu * 8 * PITCH] = e;
                float o = B4[uu + 1][0] * d0;
                o = fmaf(B4[uu + 1][1], d1, o);
                o = fmaf(B4[uu + 1][2], d2, o);
                o = fmaf(B4[uu + 1][3], d3, o);
                Gc[(uu + 1) * 8 * PITCH] = o;
            }

            __syncthreads();          // all reads of ring slot done
            if (t == 0 && n + NBUF < nchunks)
                issue_chunk(x, cta, n + NBUF, buf_s, mbar_s);
        }

        // closed-form of 32x repeated (t - min)/d
        if (t < 192) {
            const float d  = mx - mn + 1e-6f;
            const float rr = 1.0f / d;
            float r2 = rr * rr, r4 = r2 * r2, r8 = r4 * r4, r16 = r8 * r8;
            const float r32 = r16 * r16;
            aff[t] = make_float2(r32, -mn * (rr * (1.0f - r32) / (1.0f - rr)));
        }
        __syncthreads();

        // ---- Stage B: channel mix + horizontal DCT + affine + store ------
        const size_t outb = (size_t)b * 192 * 4096 + (size_t)r * 64 + half * 32 + bwB;

        #pragma unroll
        for (int q = 0; q < 3; ++q) {
            float m[8];
            #pragma unroll
            for (int c = 0; c < 3; ++c) {
                const float w = ycw[q * 3 + c];
                #pragma unroll
                for (int jj = 0; jj < 8; ++jj) {
                    const float g = G[((c * 8 + u) * 8 + jj) * PITCH + bwB];
                    m[jj] = (c == 0) ? w * g : fmaf(w, g, m[jj]);
                }
            }

            const float s0 = m[0] + m[7], s1 = m[1] + m[6], s2 = m[2] + m[5], s3 = m[3] + m[4];
            const float d0 = m[0] - m[7], d1 = m[1] - m[6], d2 = m[2] - m[5], d3 = m[3] - m[4];

            const int kbase = q * 64 + u * 8;
            #pragma unroll
            for (int vv = 0; vv < 8; vv += 2) {
                float e = B4[vv][0] * s0;
                e = fmaf(B4[vv][1], s1, e);
                e = fmaf(B4[vv][2], s2, e);
                e = fmaf(B4[vv][3], s3, e);
                float2 sb = aff[kbase + vv];
                out[outb + (size_t)(kbase + vv) * 4096] = fmaf(e, sb.x, sb.y);

                float o = B4[vv + 1][0] * d0;
                o = fmaf(B4[vv + 1][1], d1, o);
                o = fmaf(B4[vv + 1][2], d2, o);
                o = fmaf(B4[vv + 1][3], d3, o);
                sb = aff[kbase + vv + 1];
                out[outb + (size_t)(kbase + vv + 1) * 4096] = fmaf(o, sb.x, sb.y);
            }
        }
        __syncthreads();              // G + aff free for next strip
    }
}

extern "C" void kernel_launch(void* const* d_in, const int* in_sizes, int n_in,
                              void* d_out, int out_size)
{
    const float* x    = (const float*)d_in[0];
    const float* max_ = (const float*)d_in[1];
    const float* min_ = (const float*)d_in[2];
    const float* ycw  = (const float*)d_in[3];
    float* out = (float*)d_out;

    cudaFuncSetAttribute(dct_fused_kernel,
                         cudaFuncAttributeMaxDynamicSharedMemorySize, SMEM_BYTES);

    dct_fused_kernel<<<GRID, NT, SMEM_BYTES>>>(x, max_, min_, ycw, out);
}